// round 1
// baseline (speedup 1.0000x reference)
#include <cuda_runtime.h>
#include <math.h>

// Problem constants
#define B  32
#define O  64
#define I  2048
#define VO 32
#define VI 16

// P0 tiling
#define OB 4
#define IB 4

// Scratch (device globals: no allocation allowed)
__device__ float g_uhat[(size_t)B * I * O * VO];  // [b][i][o][v], 512 MB
__device__ float g_S0[B * O * VO];
__device__ float g_S1[B * O * VO];
__device__ float g_S2[B * O * VO];
__device__ float g_Vacc[B * O * VO];              // v0, then v0+v1

// ---------------------------------------------------------------------------
// Zero the accumulators (must happen every launch: graph replays reuse scratch)
// ---------------------------------------------------------------------------
__global__ void zero_kernel() {
    int idx = blockIdx.x * blockDim.x + threadIdx.x;
    if (idx < B * O * VO) {
        g_S0[idx] = 0.0f;
        g_S1[idx] = 0.0f;
        g_S2[idx] = 0.0f;
    }
}

// ---------------------------------------------------------------------------
// P0: u_hat[b,i,o,v] = sum_u W[o,i,v,u] * x[b,i,u]
//     Also accumulates S0[b,o,v] = sum_i u_hat (uniform-coupling iteration 0).
// CTA covers (OB o's) x (IB i's) x all 32 b. W tile + x tile in SMEM.
// Thread t: b = t>>3, v-quad = t&7. 64 FMA per (o,i) per thread.
// ---------------------------------------------------------------------------
__global__ void __launch_bounds__(256) p0_kernel(const float* __restrict__ W,
                                                 const float* __restrict__ x) {
    __shared__ float Ws[OB * IB * VO * VI];  // 8192 floats = 32 KB
    __shared__ float Xs[IB * B * VI];        // 2048 floats =  8 KB

    const int i0 = blockIdx.x * IB;
    const int o0 = blockIdx.y * OB;
    const int tid = threadIdx.x;

    // Load W tile: OB*IB slices of 512 floats each, coalesced float4
    for (int q = tid; q < (OB * IB * VO * VI) / 4; q += 256) {
        int slice = q >> 7;      // which (oo, ii): 128 float4 per slice
        int r = q & 127;
        int oo = slice / IB;
        int ii = slice - oo * IB;
        size_t g = ((size_t)(o0 + oo) * I + (size_t)(i0 + ii)) * (VO * VI);
        ((float4*)Ws)[q] = *(const float4*)(W + g + r * 4);
    }
    // Load x tile into [ii][b][u]
    for (int q = tid; q < (IB * B * VI) / 4; q += 256) {
        int uq = q & 3;
        int b = (q >> 2) & 31;
        int ii = q >> 7;
        float4 xv = *(const float4*)(x + ((size_t)b * I + (size_t)(i0 + ii)) * VI + uq * 4);
        *(float4*)(Xs + (ii * B + b) * VI + uq * 4) = xv;
    }
    __syncthreads();

    const int b = tid >> 3;
    const int vq = tid & 7;       // v in [4*vq, 4*vq+4)

    float s0p[OB][4];
#pragma unroll
    for (int oo = 0; oo < OB; oo++)
#pragma unroll
        for (int j = 0; j < 4; j++) s0p[oo][j] = 0.0f;

    for (int ii = 0; ii < IB; ii++) {
        float xr[VI];
#pragma unroll
        for (int k = 0; k < 4; k++) {
            float4 t4 = *(const float4*)(Xs + (ii * B + b) * VI + k * 4);
            xr[4 * k + 0] = t4.x; xr[4 * k + 1] = t4.y;
            xr[4 * k + 2] = t4.z; xr[4 * k + 3] = t4.w;
        }
#pragma unroll
        for (int oo = 0; oo < OB; oo++) {
            const float* wrow = Ws + ((oo * IB + ii) * VO + vq * 4) * VI;
            float uh0 = 0.0f, uh1 = 0.0f, uh2 = 0.0f, uh3 = 0.0f;
#pragma unroll
            for (int u = 0; u < VI; u++) {
                float xv = xr[u];
                uh0 = fmaf(wrow[0 * VI + u], xv, uh0);
                uh1 = fmaf(wrow[1 * VI + u], xv, uh1);
                uh2 = fmaf(wrow[2 * VI + u], xv, uh2);
                uh3 = fmaf(wrow[3 * VI + u], xv, uh3);
            }
            size_t oidx = (((size_t)b * I + (size_t)(i0 + ii)) * O + (size_t)(o0 + oo)) * VO
                        + (size_t)(vq * 4);
            *(float4*)(g_uhat + oidx) = make_float4(uh0, uh1, uh2, uh3);
            s0p[oo][0] += uh0; s0p[oo][1] += uh1;
            s0p[oo][2] += uh2; s0p[oo][3] += uh3;
        }
    }
#pragma unroll
    for (int oo = 0; oo < OB; oo++)
#pragma unroll
        for (int j = 0; j < 4; j++)
            atomicAdd(&g_S0[(b * O + (o0 + oo)) * VO + vq * 4 + j], s0p[oo][j]);
}

// ---------------------------------------------------------------------------
// P1/P2: one routing pass. For each (b,i): a[o] = u_hat[b,i,o,:] . Vacc[b,o,:]
// softmax over o, accumulate c[o]*u_hat into S{pass}.
// CTA: one b, 32 i's. Thread t: o = t>>2, owns 8 v's ((t&3)*8 ..).
// ---------------------------------------------------------------------------
__global__ void __launch_bounds__(256) p1_kernel(int pass) {
    __shared__ float Vs[O * VO];   // 8 KB
    __shared__ float aval[O];
    __shared__ float red[2];       // [max, 1/sumexp]

    const int b = blockIdx.y;
    const int i0 = blockIdx.x * 32;
    const int t = threadIdx.x;
    float* Sout = (pass == 1) ? g_S1 : g_S2;

    for (int q = t; q < O * VO; q += 256) Vs[q] = g_Vacc[b * O * VO + q];
    __syncthreads();

    const int o = t >> 2;
    const int v0 = (t & 3) * 8;
    const float* vv = Vs + o * VO + v0;

    float sa0 = 0.f, sa1 = 0.f, sa2 = 0.f, sa3 = 0.f;
    float sa4 = 0.f, sa5 = 0.f, sa6 = 0.f, sa7 = 0.f;

    for (int ic = 0; ic < 32; ic++) {
        size_t base = (((size_t)b * I + (size_t)(i0 + ic)) * O + (size_t)o) * VO + (size_t)v0;
        float4 A  = *(const float4*)(g_uhat + base);
        float4 Bv = *(const float4*)(g_uhat + base + 4);

        float d = A.x * vv[0];
        d = fmaf(A.y,  vv[1], d);
        d = fmaf(A.z,  vv[2], d);
        d = fmaf(A.w,  vv[3], d);
        d = fmaf(Bv.x, vv[4], d);
        d = fmaf(Bv.y, vv[5], d);
        d = fmaf(Bv.z, vv[6], d);
        d = fmaf(Bv.w, vv[7], d);
        // reduce partial dot across the 4 threads sharing this o
        d += __shfl_xor_sync(0xffffffffu, d, 1);
        d += __shfl_xor_sync(0xffffffffu, d, 2);

        if ((t & 3) == 0) aval[o] = d;
        __syncthreads();

        if (t < 32) {
            float a0 = aval[t], a1 = aval[t + 32];
            float m = fmaxf(a0, a1);
#pragma unroll
            for (int off = 16; off; off >>= 1)
                m = fmaxf(m, __shfl_xor_sync(0xffffffffu, m, off));
            float e = __expf(a0 - m) + __expf(a1 - m);
#pragma unroll
            for (int off = 16; off; off >>= 1)
                e += __shfl_xor_sync(0xffffffffu, e, off);
            if (t == 0) { red[0] = m; red[1] = 1.0f / e; }
        }
        __syncthreads();

        float c = __expf(d - red[0]) * red[1];
        sa0 = fmaf(c, A.x,  sa0);
        sa1 = fmaf(c, A.y,  sa1);
        sa2 = fmaf(c, A.z,  sa2);
        sa3 = fmaf(c, A.w,  sa3);
        sa4 = fmaf(c, Bv.x, sa4);
        sa5 = fmaf(c, Bv.y, sa5);
        sa6 = fmaf(c, Bv.z, sa6);
        sa7 = fmaf(c, Bv.w, sa7);
    }

    float* sp = Sout + (b * O + o) * VO + v0;
    atomicAdd(&sp[0], sa0); atomicAdd(&sp[1], sa1);
    atomicAdd(&sp[2], sa2); atomicAdd(&sp[3], sa3);
    atomicAdd(&sp[4], sa4); atomicAdd(&sp[5], sa5);
    atomicAdd(&sp[6], sa6); atomicAdd(&sp[7], sa7);
}

// ---------------------------------------------------------------------------
// Squash kernel. which==0: v0=squash(S0/64), Vacc=v0.
//                which==1: v1=squash(S1),   Vacc+=v1.
//                which==2: v2=squash(S2) -> out.
// One warp per (b,o) pair; lane = v.
// ---------------------------------------------------------------------------
__global__ void kv_kernel(int which, float* __restrict__ out) {
    int wid = threadIdx.x >> 5;
    int lane = threadIdx.x & 31;
    int pair = blockIdx.x * (blockDim.x >> 5) + wid;
    if (pair >= B * O) return;
    int idx = pair * VO + lane;

    float s;
    if (which == 0)      s = g_S0[idx] * (1.0f / (float)O);
    else if (which == 1) s = g_S1[idx];
    else                 s = g_S2[idx];

    float sq = s * s;
#pragma unroll
    for (int off = 16; off; off >>= 1)
        sq += __shfl_xor_sync(0xffffffffu, sq, off);

    float scale = (sq / (1.0f + sq)) * rsqrtf(sq + 1e-8f);
    float v = s * scale;

    if (which == 0)      g_Vacc[idx] = v;
    else if (which == 1) g_Vacc[idx] += v;
    else                 out[idx] = v;
}

// ---------------------------------------------------------------------------
extern "C" void kernel_launch(void* const* d_in, const int* in_sizes, int n_in,
                              void* d_out, int out_size) {
    const float* x;
    const float* W;
    if (in_sizes[0] == B * I * VI) {
        x = (const float*)d_in[0];
        W = (const float*)d_in[1];
    } else {
        x = (const float*)d_in[1];
        W = (const float*)d_in[0];
    }
    float* out = (float*)d_out;

    zero_kernel<<<(B * O * VO + 255) / 256, 256>>>();

    // P0: u_hat + S0 (iteration 0, uniform coupling)
    p0_kernel<<<dim3(I / IB, O / OB), 256>>>(W, x);
    kv_kernel<<<64, 1024>>>(0, out);   // v0 = squash(S0/64); Vacc = v0

    // Iteration 1: logits = u_hat . v0
    p1_kernel<<<dim3(I / 32, B), 256>>>(1);
    kv_kernel<<<64, 1024>>>(1, out);   // v1 = squash(S1); Vacc = v0 + v1

    // Iteration 2: logits = u_hat . (v0 + v1)  (b is linear in accumulated v)
    p1_kernel<<<dim3(I / 32, B), 256>>>(2);
    kv_kernel<<<64, 1024>>>(2, out);   // out = squash(S2)
}

// round 3
// speedup vs baseline: 4.2503x; 4.2503x over previous
#include <cuda_runtime.h>
#include <cuda_fp16.h>
#include <math.h>

// Problem constants
#define B  32
#define O  64
#define I  2048
#define VO 32
#define VI 16

// Scratch (device globals: no allocation allowed)
__device__ __half g_uhat[(size_t)B * I * O * VO];  // [b][i][o][v], fp16, 256 MB
__device__ float g_S0[B * O * VO];
__device__ float g_S1[B * O * VO];
__device__ float g_S2[B * O * VO];
__device__ float g_Vacc[B * O * VO];               // v0, then v0+v1

// ---------------------------------------------------------------------------
// Zero the atomic accumulators (graph replays reuse scratch)
// ---------------------------------------------------------------------------
__global__ void zero_kernel() {
    int idx = blockIdx.x * blockDim.x + threadIdx.x;
    if (idx < B * O * VO) {
        g_S1[idx] = 0.0f;
        g_S2[idx] = 0.0f;
    }
}

// ---------------------------------------------------------------------------
// P0: u_hat[b,i,o,v] = sum_u W[o,i,v,u] * x[b,i,u], stored fp16.
// Grid: (I, O/32). CTA 256 threads: thread = (o_local = t>>3, vq = t&7).
// Each thread holds its 64 W floats (4 v-rows x 16 u) in registers (W read
// exactly once from DRAM, coalesced), then loops b=0..31 reading x via
// broadcast LDS.
// ---------------------------------------------------------------------------
__global__ void __launch_bounds__(256) p0_kernel(const float* __restrict__ W,
                                                 const float* __restrict__ x) {
    __shared__ float Xs[B * VI];   // 2 KB: x[b][u] for this i

    const int i  = blockIdx.x;
    const int o  = blockIdx.y * 32 + (threadIdx.x >> 3);
    const int vq = threadIdx.x & 7;

    // Load x tile (all 32 b's for this i): 512 floats = 128 float4
    if (threadIdx.x < 128) {
        int b = threadIdx.x >> 2;
        int q = threadIdx.x & 3;
        *(float4*)(Xs + b * VI + q * 4) =
            *(const float4*)(x + ((size_t)b * I + i) * VI + q * 4);
    }

    // Load this thread's W block: rows v = vq*4 .. vq*4+3, 16 u each
    float wr[4][VI];
    const size_t wbase = ((size_t)o * I + i) * (VO * VI) + (size_t)(vq * 4) * VI;
#pragma unroll
    for (int r = 0; r < 4; r++) {
#pragma unroll
        for (int q = 0; q < 4; q++) {
            float4 t4 = *(const float4*)(W + wbase + r * VI + q * 4);
            wr[r][q * 4 + 0] = t4.x; wr[r][q * 4 + 1] = t4.y;
            wr[r][q * 4 + 2] = t4.z; wr[r][q * 4 + 3] = t4.w;
        }
    }
    __syncthreads();

    uint2* outp = (uint2*)g_uhat;

#pragma unroll 2
    for (int b = 0; b < B; b++) {
        float xr[VI];
#pragma unroll
        for (int q = 0; q < 4; q++) {
            float4 t4 = *(const float4*)(Xs + b * VI + q * 4);
            xr[q * 4 + 0] = t4.x; xr[q * 4 + 1] = t4.y;
            xr[q * 4 + 2] = t4.z; xr[q * 4 + 3] = t4.w;
        }
        float uh0 = 0.f, uh1 = 0.f, uh2 = 0.f, uh3 = 0.f;
#pragma unroll
        for (int u = 0; u < VI; u++) {
            float xv = xr[u];
            uh0 = fmaf(wr[0][u], xv, uh0);
            uh1 = fmaf(wr[1][u], xv, uh1);
            uh2 = fmaf(wr[2][u], xv, uh2);
            uh3 = fmaf(wr[3][u], xv, uh3);
        }
        __half2 h0 = __floats2half2_rn(uh0, uh1);
        __half2 h1 = __floats2half2_rn(uh2, uh3);
        uint2 pk;
        pk.x = *(unsigned int*)&h0;
        pk.y = *(unsigned int*)&h1;
        // half index: ((b*I+i)*O + o)*VO + vq*4  -> uint2 index = /4
        size_t hidx = (((size_t)b * I + i) * O + o) * VO + (size_t)vq * 4;
        outp[hidx >> 2] = pk;
    }
}

// ---------------------------------------------------------------------------
// S0 pass: S0[b,o,v] = sum_i u_hat[b,i,o,v]. No atomics: thread owns (b,o,p)
// where p is a half2 column (2 v's). 32768 threads, each loops over i.
// Warp accesses are fully coalesced (p,o contiguous).
// ---------------------------------------------------------------------------
__global__ void __launch_bounds__(256) s0_kernel() {
    int t = blockIdx.x * blockDim.x + threadIdx.x;   // 0 .. 32767
    int p = t & 15;            // half2 column (v pair)
    int o = (t >> 4) & 63;
    int b = t >> 10;

    const __half2* up = (const __half2*)g_uhat;
    size_t base = ((size_t)b * I * O + o) * (VO / 2) + p;   // i = 0
    const size_t istride = (size_t)O * (VO / 2);            // per-i stride in half2

    float ax = 0.f, ay = 0.f;
#pragma unroll 8
    for (int i = 0; i < I; i++) {
        float2 f = __half22float2(up[base + (size_t)i * istride]);
        ax += f.x; ay += f.y;
    }
    float2* sp = (float2*)g_S0;
    sp[(size_t)(b * O + o) * (VO / 2) + p] = make_float2(ax, ay);
}

// ---------------------------------------------------------------------------
// P1/P2: one routing pass, fully warp-autonomous (no __syncthreads).
// Warp handles (b, 32 i's). Lane owns o0=lane and o1=lane+32: full 32-length
// dots per lane, softmax over the 64 o's via warp shuffles, S accumulated in
// registers, one atomicAdd tail per element.
// Row = 32 halves = 4 uint4; o1 row at +32*4 = +128 uint4.
// ---------------------------------------------------------------------------
__global__ void __launch_bounds__(128) p1_kernel(int pass) {
    const int gw = blockIdx.x * (blockDim.x >> 5) + (threadIdx.x >> 5);
    const int lane = threadIdx.x & 31;
    const int b = gw >> 6;            // 32 b's
    const int i0 = (gw & 63) * 32;    // 64 chunks of 32 i's
    float* Sout = (pass == 1) ? g_S1 : g_S2;

    // Vacc rows for o0=lane and o1=lane+32, in registers (fp32)
    float va[VO], vb[VO];
    {
        const float4* vp = (const float4*)(g_Vacc + (size_t)(b * O + lane) * VO);
        const float4* wp = (const float4*)(g_Vacc + (size_t)(b * O + lane + 32) * VO);
#pragma unroll
        for (int j = 0; j < 8; j++) {
            float4 t4 = vp[j];
            va[4 * j + 0] = t4.x; va[4 * j + 1] = t4.y; va[4 * j + 2] = t4.z; va[4 * j + 3] = t4.w;
            float4 s4 = wp[j];
            vb[4 * j + 0] = s4.x; vb[4 * j + 1] = s4.y; vb[4 * j + 2] = s4.z; vb[4 * j + 3] = s4.w;
        }
    }

    float sa[VO], sb[VO];
#pragma unroll
    for (int v = 0; v < VO; v++) { sa[v] = 0.f; sb[v] = 0.f; }

    for (int ic = 0; ic < 32; ic++) {
        const int i = i0 + ic;
        const uint4* up = (const uint4*)(g_uhat + (((size_t)b * I + i) * O + lane) * VO);
        // o0 row: 4 uint4; o1 row: +128 uint4
        uint4 h0 = up[0];
        uint4 h1 = up[1];
        uint4 h2 = up[2];
        uint4 h3 = up[3];
        uint4 g0 = up[128];
        uint4 g1 = up[129];
        uint4 g2 = up[130];
        uint4 g3 = up[131];

        unsigned int r0[16] = {h0.x, h0.y, h0.z, h0.w, h1.x, h1.y, h1.z, h1.w,
                               h2.x, h2.y, h2.z, h2.w, h3.x, h3.y, h3.z, h3.w};
        unsigned int r1[16] = {g0.x, g0.y, g0.z, g0.w, g1.x, g1.y, g1.z, g1.w,
                               g2.x, g2.y, g2.z, g2.w, g3.x, g3.y, g3.z, g3.w};

        float d0 = 0.f, d1 = 0.f;
#pragma unroll
        for (int j = 0; j < 16; j++) {
            float2 f0 = __half22float2(*(const __half2*)&r0[j]);
            d0 = fmaf(f0.x, va[2 * j + 0], d0);
            d0 = fmaf(f0.y, va[2 * j + 1], d0);
            float2 f1 = __half22float2(*(const __half2*)&r1[j]);
            d1 = fmaf(f1.x, vb[2 * j + 0], d1);
            d1 = fmaf(f1.y, vb[2 * j + 1], d1);
        }

        // softmax over the 64 o's (2 per lane) via warp shuffles
        float m = fmaxf(d0, d1);
#pragma unroll
        for (int off = 16; off; off >>= 1)
            m = fmaxf(m, __shfl_xor_sync(0xffffffffu, m, off));
        float e0 = __expf(d0 - m);
        float e1 = __expf(d1 - m);
        float es = e0 + e1;
#pragma unroll
        for (int off = 16; off; off >>= 1)
            es += __shfl_xor_sync(0xffffffffu, es, off);
        float inv = __frcp_rn(es);
        float c0 = e0 * inv;
        float c1 = e1 * inv;

#pragma unroll
        for (int j = 0; j < 16; j++) {
            float2 f0 = __half22float2(*(const __half2*)&r0[j]);
            sa[2 * j + 0] = fmaf(c0, f0.x, sa[2 * j + 0]);
            sa[2 * j + 1] = fmaf(c0, f0.y, sa[2 * j + 1]);
            float2 f1 = __half22float2(*(const __half2*)&r1[j]);
            sb[2 * j + 0] = fmaf(c1, f1.x, sb[2 * j + 0]);
            sb[2 * j + 1] = fmaf(c1, f1.y, sb[2 * j + 1]);
        }
    }

    float* sp0 = Sout + (size_t)(b * O + lane) * VO;
    float* sp1 = Sout + (size_t)(b * O + lane + 32) * VO;
#pragma unroll
    for (int v = 0; v < VO; v++) {
        atomicAdd(&sp0[v], sa[v]);
        atomicAdd(&sp1[v], sb[v]);
    }
}

// ---------------------------------------------------------------------------
// Squash. which==0: v0=squash(S0/64), Vacc=v0.
//         which==1: v1=squash(S1),   Vacc+=v1.
//         which==2: out=squash(S2).
// One warp per (b,o); lane = v.
// ---------------------------------------------------------------------------
__global__ void kv_kernel(int which, float* __restrict__ out) {
    int wid = threadIdx.x >> 5;
    int lane = threadIdx.x & 31;
    int pair = blockIdx.x * (blockDim.x >> 5) + wid;
    if (pair >= B * O) return;
    int idx = pair * VO + lane;

    float s;
    if (which == 0)      s = g_S0[idx] * (1.0f / (float)O);
    else if (which == 1) s = g_S1[idx];
    else                 s = g_S2[idx];

    float sq = s * s;
#pragma unroll
    for (int off = 16; off; off >>= 1)
        sq += __shfl_xor_sync(0xffffffffu, sq, off);

    float scale = (sq / (1.0f + sq)) * rsqrtf(sq + 1e-8f);
    float v = s * scale;

    if (which == 0)      g_Vacc[idx] = v;
    else if (which == 1) g_Vacc[idx] += v;
    else                 out[idx] = v;
}

// ---------------------------------------------------------------------------
extern "C" void kernel_launch(void* const* d_in, const int* in_sizes, int n_in,
                              void* d_out, int out_size) {
    const float* x;
    const float* W;
    if (in_sizes[0] == B * I * VI) {
        x = (const float*)d_in[0];
        W = (const float*)d_in[1];
    } else {
        x = (const float*)d_in[1];
        W = (const float*)d_in[0];
    }
    float* out = (float*)d_out;

    zero_kernel<<<(B * O * VO + 255) / 256, 256>>>();

    // P0: u_hat (fp16)
    p0_kernel<<<dim3(I, O / 32), 256>>>(W, x);

    // Iteration 0 (uniform coupling): S0 = sum_i u_hat
    s0_kernel<<<(B * O * (VO / 2)) / 256, 256>>>();
    kv_kernel<<<64, 1024>>>(0, out);   // v0 = squash(S0/64); Vacc = v0

    // Iteration 1: logits = u_hat . v0
    p1_kernel<<<512, 128>>>(1);
    kv_kernel<<<64, 1024>>>(1, out);   // v1 = squash(S1); Vacc = v0 + v1

    // Iteration 2: logits = u_hat . (v0 + v1)
    p1_kernel<<<512, 128>>>(2);
    kv_kernel<<<64, 1024>>>(2, out);   // out = squash(S2)
}

// round 4
// speedup vs baseline: 5.4753x; 1.2882x over previous
#include <cuda_runtime.h>
#include <cuda_fp16.h>
#include <math.h>

// Problem constants
#define B  32
#define O  64
#define I  2048
#define VO 32
#define VI 16

typedef unsigned long long u64;

// Scratch (device globals: no allocation allowed)
__device__ __half g_uhat[(size_t)B * I * O * VO];  // [b][i][o][v], fp16, 256 MB
__device__ float g_S0[B * O * VO];
__device__ float g_S1[B * O * VO];
__device__ float g_S2[B * O * VO];
__device__ float g_Vacc[B * O * VO];               // v0, then v0+v1

// ---------------------------------------------------------------------------
// f32x2 packed helpers (Blackwell dual FP32 FMA)
// ---------------------------------------------------------------------------
__device__ __forceinline__ u64 ffma2(u64 a, u64 b, u64 c) {
    u64 d;
    asm("fma.rn.f32x2 %0,%1,%2,%3;" : "=l"(d) : "l"(a), "l"(b), "l"(c));
    return d;
}
__device__ __forceinline__ void upk2(u64 v, float& lo, float& hi) {
    asm("mov.b64 {%0,%1},%2;" : "=f"(lo), "=f"(hi) : "l"(v));
}

// ---------------------------------------------------------------------------
// Zero the atomic accumulators (graph replays reuse scratch). Idempotent —
// launched 5x as padding so p0_kernel is launch index 5 (ncu -s 5 -c 1).
// ---------------------------------------------------------------------------
__global__ void zero_kernel() {
    int idx = blockIdx.x * blockDim.x + threadIdx.x;
    if (idx < B * O * VO) {
        g_S0[idx] = 0.0f;
        g_S1[idx] = 0.0f;
        g_S2[idx] = 0.0f;
    }
}

// ---------------------------------------------------------------------------
// P0: u_hat[b,i,o,v] = sum_u W[o,i,v,u] * x[b,i,u], stored fp16.
// Grid: (I, O/32). CTA 256 threads: thread = (o_local = t>>3, vq = t&7).
// Thread holds its 64 W floats as 32 packed f32x2 (pairs over u). Per b:
// 32 FFMA2 (even/odd-u partial sums) + 4 lane-adds. W read once from DRAM.
// ---------------------------------------------------------------------------
__global__ void __launch_bounds__(256) p0_kernel(const float* __restrict__ W,
                                                 const float* __restrict__ x) {
    __shared__ float Xs[B * VI];   // 2 KB: x[b][u] for this i

    const int i  = blockIdx.x;
    const int o  = blockIdx.y * 32 + (threadIdx.x >> 3);
    const int vq = threadIdx.x & 7;

    // Load x tile (all 32 b's for this i): 512 floats = 128 float4
    if (threadIdx.x < 128) {
        int b = threadIdx.x >> 2;
        int q = threadIdx.x & 3;
        *(float4*)(Xs + b * VI + q * 4) =
            *(const float4*)(x + ((size_t)b * I + i) * VI + q * 4);
    }

    // Load this thread's W block: rows v = vq*4 .. vq*4+3 (64 consecutive
    // floats = 32 f32x2, naturally paired over u).
    u64 wp[4][8];
    const size_t wbase = ((size_t)o * I + i) * (VO * VI) + (size_t)(vq * 4) * VI;
#pragma unroll
    for (int r = 0; r < 4; r++) {
#pragma unroll
        for (int q = 0; q < 4; q++) {
            ulonglong2 t2 = *(const ulonglong2*)(W + wbase + r * VI + q * 4);
            wp[r][q * 2 + 0] = t2.x;
            wp[r][q * 2 + 1] = t2.y;
        }
    }
    __syncthreads();

#pragma unroll 2
    for (int b = 0; b < B; b++) {
        u64 xp[8];
#pragma unroll
        for (int q = 0; q < 4; q++) {
            ulonglong2 t2 = *(const ulonglong2*)(Xs + b * VI + q * 4);
            xp[q * 2 + 0] = t2.x;
            xp[q * 2 + 1] = t2.y;
        }
        u64 a0 = 0ull, a1 = 0ull, a2 = 0ull, a3 = 0ull;
#pragma unroll
        for (int j = 0; j < 8; j++) {
            a0 = ffma2(wp[0][j], xp[j], a0);
            a1 = ffma2(wp[1][j], xp[j], a1);
            a2 = ffma2(wp[2][j], xp[j], a2);
            a3 = ffma2(wp[3][j], xp[j], a3);
        }
        float l0, h0, l1, h1, l2, h2, l3, h3;
        upk2(a0, l0, h0); upk2(a1, l1, h1);
        upk2(a2, l2, h2); upk2(a3, l3, h3);
        float uh0 = l0 + h0, uh1 = l1 + h1, uh2 = l2 + h2, uh3 = l3 + h3;

        __half2 p0h = __floats2half2_rn(uh0, uh1);
        __half2 p1h = __floats2half2_rn(uh2, uh3);
        float2 pk;
        pk.x = __uint_as_float(*(unsigned int*)&p0h);
        pk.y = __uint_as_float(*(unsigned int*)&p1h);
        // half index: ((b*I+i)*O + o)*VO + vq*4
        size_t hidx = (((size_t)b * I + i) * O + o) * VO + (size_t)vq * 4;
        __stcs((float2*)(g_uhat + hidx), pk);
    }
}

// ---------------------------------------------------------------------------
// S0 pass: S0[b,o,v] = sum_i u_hat[b,i,o,v]. Thread owns (b,o,q,c) where q is
// a uint2 column (4 v's) and c one of 4 i-chunks; atomicAdd tail into zeroed
// S0. 65536 threads -> ~28KB DRAM bytes in flight per SM (saturates HBM).
// ---------------------------------------------------------------------------
__global__ void __launch_bounds__(256) s0_kernel() {
    int t = blockIdx.x * 256 + threadIdx.x;   // 0 .. 65535
    int q = t & 7;             // uint2 column (4 v's)
    int o = (t >> 3) & 63;
    int c = (t >> 9) & 3;      // i chunk
    int b = t >> 11;

    const uint2* up = (const uint2*)g_uhat;
    // half idx: ((b*I + i)*O + o)*32 + q*4  -> uint2 idx = /4
    size_t base = (((size_t)b * I + (size_t)c * 512) * O + (size_t)o) * 8 + q;
    const size_t istride = (size_t)O * 8;

    float a0 = 0.f, a1 = 0.f, a2 = 0.f, a3 = 0.f;
#pragma unroll 8
    for (int i = 0; i < 512; i++) {
        uint2 h = __ldcs(&up[base + (size_t)i * istride]);
        float2 f0 = __half22float2(*(const __half2*)&h.x);
        float2 f1 = __half22float2(*(const __half2*)&h.y);
        a0 += f0.x; a1 += f0.y; a2 += f1.x; a3 += f1.y;
    }
    float* sp = g_S0 + (size_t)(b * O + o) * VO + q * 4;
    atomicAdd(&sp[0], a0); atomicAdd(&sp[1], a1);
    atomicAdd(&sp[2], a2); atomicAdd(&sp[3], a3);
}

// ---------------------------------------------------------------------------
// P1/P2: one routing pass, fully warp-autonomous (no __syncthreads).
// Warp handles (b, 32 i's). Lane owns o0=lane and o1=lane+32: full 32-length
// dots per lane, softmax over the 64 o's via warp shuffles, S accumulated in
// registers, one atomicAdd tail per element.
// ---------------------------------------------------------------------------
__global__ void __launch_bounds__(128) p1_kernel(int pass) {
    const int gw = blockIdx.x * (blockDim.x >> 5) + (threadIdx.x >> 5);
    const int lane = threadIdx.x & 31;
    const int b = gw >> 6;            // 32 b's
    const int i0 = (gw & 63) * 32;    // 64 chunks of 32 i's
    float* Sout = (pass == 1) ? g_S1 : g_S2;

    // Vacc rows for o0=lane and o1=lane+32, in registers (fp32)
    float va[VO], vb[VO];
    {
        const float4* vp = (const float4*)(g_Vacc + (size_t)(b * O + lane) * VO);
        const float4* wp = (const float4*)(g_Vacc + (size_t)(b * O + lane + 32) * VO);
#pragma unroll
        for (int j = 0; j < 8; j++) {
            float4 t4 = vp[j];
            va[4 * j + 0] = t4.x; va[4 * j + 1] = t4.y; va[4 * j + 2] = t4.z; va[4 * j + 3] = t4.w;
            float4 s4 = wp[j];
            vb[4 * j + 0] = s4.x; vb[4 * j + 1] = s4.y; vb[4 * j + 2] = s4.z; vb[4 * j + 3] = s4.w;
        }
    }

    float sa[VO], sb[VO];
#pragma unroll
    for (int v = 0; v < VO; v++) { sa[v] = 0.f; sb[v] = 0.f; }

    for (int ic = 0; ic < 32; ic++) {
        const int i = i0 + ic;
        const uint4* up = (const uint4*)(g_uhat + (((size_t)b * I + i) * O + lane) * VO);
        // o0 row: 4 uint4; o1 row: +128 uint4
        uint4 h0 = __ldcs(up + 0);
        uint4 h1 = __ldcs(up + 1);
        uint4 h2 = __ldcs(up + 2);
        uint4 h3 = __ldcs(up + 3);
        uint4 g0 = __ldcs(up + 128);
        uint4 g1 = __ldcs(up + 129);
        uint4 g2 = __ldcs(up + 130);
        uint4 g3 = __ldcs(up + 131);

        unsigned int r0[16] = {h0.x, h0.y, h0.z, h0.w, h1.x, h1.y, h1.z, h1.w,
                               h2.x, h2.y, h2.z, h2.w, h3.x, h3.y, h3.z, h3.w};
        unsigned int r1[16] = {g0.x, g0.y, g0.z, g0.w, g1.x, g1.y, g1.z, g1.w,
                               g2.x, g2.y, g2.z, g2.w, g3.x, g3.y, g3.z, g3.w};

        float d0 = 0.f, d1 = 0.f;
#pragma unroll
        for (int j = 0; j < 16; j++) {
            float2 f0 = __half22float2(*(const __half2*)&r0[j]);
            d0 = fmaf(f0.x, va[2 * j + 0], d0);
            d0 = fmaf(f0.y, va[2 * j + 1], d0);
            float2 f1 = __half22float2(*(const __half2*)&r1[j]);
            d1 = fmaf(f1.x, vb[2 * j + 0], d1);
            d1 = fmaf(f1.y, vb[2 * j + 1], d1);
        }

        // softmax over the 64 o's (2 per lane) via warp shuffles
        float m = fmaxf(d0, d1);
#pragma unroll
        for (int off = 16; off; off >>= 1)
            m = fmaxf(m, __shfl_xor_sync(0xffffffffu, m, off));
        float e0 = __expf(d0 - m);
        float e1 = __expf(d1 - m);
        float es = e0 + e1;
#pragma unroll
        for (int off = 16; off; off >>= 1)
            es += __shfl_xor_sync(0xffffffffu, es, off);
        float inv = __frcp_rn(es);
        float c0 = e0 * inv;
        float c1 = e1 * inv;

#pragma unroll
        for (int j = 0; j < 16; j++) {
            float2 f0 = __half22float2(*(const __half2*)&r0[j]);
            sa[2 * j + 0] = fmaf(c0, f0.x, sa[2 * j + 0]);
            sa[2 * j + 1] = fmaf(c0, f0.y, sa[2 * j + 1]);
            float2 f1 = __half22float2(*(const __half2*)&r1[j]);
            sb[2 * j + 0] = fmaf(c1, f1.x, sb[2 * j + 0]);
            sb[2 * j + 1] = fmaf(c1, f1.y, sb[2 * j + 1]);
        }
    }

    float* sp0 = Sout + (size_t)(b * O + lane) * VO;
    float* sp1 = Sout + (size_t)(b * O + lane + 32) * VO;
#pragma unroll
    for (int v = 0; v < VO; v++) {
        atomicAdd(&sp0[v], sa[v]);
        atomicAdd(&sp1[v], sb[v]);
    }
}

// ---------------------------------------------------------------------------
// Squash. which==0: v0=squash(S0/64), Vacc=v0.
//         which==1: v1=squash(S1),   Vacc+=v1.
//         which==2: out=squash(S2).
// One warp per (b,o); lane = v.
// ---------------------------------------------------------------------------
__global__ void kv_kernel(int which, float* __restrict__ out) {
    int wid = threadIdx.x >> 5;
    int lane = threadIdx.x & 31;
    int pair = blockIdx.x * (blockDim.x >> 5) + wid;
    if (pair >= B * O) return;
    int idx = pair * VO + lane;

    float s;
    if (which == 0)      s = g_S0[idx] * (1.0f / (float)O);
    else if (which == 1) s = g_S1[idx];
    else                 s = g_S2[idx];

    float sq = s * s;
#pragma unroll
    for (int off = 16; off; off >>= 1)
        sq += __shfl_xor_sync(0xffffffffu, sq, off);

    float scale = (sq / (1.0f + sq)) * rsqrtf(sq + 1e-8f);
    float v = s * scale;

    if (which == 0)      g_Vacc[idx] = v;
    else if (which == 1) g_Vacc[idx] += v;
    else                 out[idx] = v;
}

// ---------------------------------------------------------------------------
extern "C" void kernel_launch(void* const* d_in, const int* in_sizes, int n_in,
                              void* d_out, int out_size) {
    const float* x;
    const float* W;
    if (in_sizes[0] == B * I * VI) {
        x = (const float*)d_in[0];
        W = (const float*)d_in[1];
    } else {
        x = (const float*)d_in[1];
        W = (const float*)d_in[0];
    }
    float* out = (float*)d_out;

    // 5 idempotent zero launches: needed once for S0/S1/S2; repeated so that
    // p0_kernel sits at launch index 5 for ncu (-s 5 -c 1) profiling.
    for (int r = 0; r < 5; r++)
        zero_kernel<<<(B * O * VO + 255) / 256, 256>>>();

    // P0: u_hat (fp16), launch #5 -> profiled
    p0_kernel<<<dim3(I, O / 32), 256>>>(W, x);

    // Iteration 0 (uniform coupling): S0 = sum_i u_hat
    s0_kernel<<<256, 256>>>();
    kv_kernel<<<64, 1024>>>(0, out);   // v0 = squash(S0/64); Vacc = v0

    // Iteration 1: logits = u_hat . v0
    p1_kernel<<<512, 128>>>(1);
    kv_kernel<<<64, 1024>>>(1, out);   // v1 = squash(S1); Vacc = v0 + v1

    // Iteration 2: logits = u_hat . (v0 + v1)
    p1_kernel<<<512, 128>>>(2);
    kv_kernel<<<64, 1024>>>(2, out);   // out = squash(S2)
}

// round 5
// speedup vs baseline: 5.5014x; 1.0048x over previous
#include <cuda_runtime.h>
#include <cuda_fp16.h>
#include <math.h>

// Problem constants
#define B  32
#define O  64
#define I  2048
#define VO 32
#define VI 16

#define OG 16   // o's per p0 CTA

typedef unsigned long long u64;

// Scratch (device globals: no allocation allowed)
__device__ __half g_uhat[(size_t)B * I * O * VO];  // [b][i][o][v], fp16, 256 MB
__device__ float g_S0[B * O * VO];
__device__ float g_S1[B * O * VO];
__device__ float g_S2[B * O * VO];
__device__ float g_Vacc[B * O * VO];               // v0, then v0+v1

// ---------------------------------------------------------------------------
// helpers
// ---------------------------------------------------------------------------
__device__ __forceinline__ u64 ffma2(u64 a, u64 b, u64 c) {
    u64 d;
    asm("fma.rn.f32x2 %0,%1,%2,%3;" : "=l"(d) : "l"(a), "l"(b), "l"(c));
    return d;
}
__device__ __forceinline__ void upk2(u64 v, float& lo, float& hi) {
    asm("mov.b64 {%0,%1},%2;" : "=f"(lo), "=f"(hi) : "l"(v));
}
__device__ __forceinline__ unsigned int smem_u32(const void* p) {
    return (unsigned int)__cvta_generic_to_shared(p);
}
__device__ __forceinline__ void cp_async16(unsigned int s, const void* g) {
    asm volatile("cp.async.cg.shared.global [%0], [%1], 16;" :: "r"(s), "l"(g));
}
__device__ __forceinline__ void cp_async_wait_all() {
    asm volatile("cp.async.commit_group;");
    asm volatile("cp.async.wait_group 0;");
}
// XOR-swizzle: spread the 256B-stride (bits[8:10]) into the 16B-chunk selector
__device__ __forceinline__ unsigned int swz(unsigned int off) {
    return off ^ (((off >> 8) & 7u) << 4);
}

// ---------------------------------------------------------------------------
// Zero the atomic accumulators (graph replays reuse scratch)
// ---------------------------------------------------------------------------
__global__ void zero_kernel() {
    int idx = blockIdx.x * blockDim.x + threadIdx.x;
    if (idx < B * O * VO) {
        g_S0[idx] = 0.0f;
        g_S1[idx] = 0.0f;
        g_S2[idx] = 0.0f;
    }
}

// ---------------------------------------------------------------------------
// P0: u_hat[b,i,o,v] = sum_u W[o,i,v,u] * x[b,i,u], stored fp16.
// Grid (I, O/OG), 128 threads. W tile (OG o's, one i) = 32KB staged via
// cp.async into swizzled SMEM (coalesced, line-granular), then each thread
// LDSes its 64 floats conflict-free into regs and runs the 32-b FFMA2 loop.
// ---------------------------------------------------------------------------
__global__ void __launch_bounds__(128) p0_kernel(const float* __restrict__ W,
                                                 const float* __restrict__ x) {
    __shared__ float Ws[OG * 512];   // 32 KB
    __shared__ float Xs[B * VI];     // 2 KB

    const int i   = blockIdx.x;
    const int o0  = blockIdx.y * OG;
    const int tid = threadIdx.x;

    const unsigned int sW = smem_u32(Ws);
    const unsigned int sX = smem_u32(Xs);

    // W tile: chunk (tid, k) <- W[(o0+k)*I + i] row, bytes [tid*16, +16)
#pragma unroll
    for (int k = 0; k < OG; k++) {
        unsigned int loff = (unsigned int)(k * 2048 + tid * 16);
        cp_async16(sW + swz(loff),
                   (const char*)W + (((size_t)(o0 + k) * I + i) * 512 + tid * 4) * 4);
    }
    // x tile: thread tid -> b = tid>>2, quad q = tid&3
    {
        int b = tid >> 2, q = tid & 3;
        cp_async16(sX + (unsigned int)(tid * 16),
                   x + ((size_t)b * I + i) * VI + q * 4);
    }
    cp_async_wait_all();
    __syncthreads();

    // Per-thread W regs: rows v = vq*4..vq*4+3 of o = o0+ol (64 floats = 32 f32x2)
    const int ol = tid >> 3;
    const int vq = tid & 7;
    u64 wp[4][8];
    {
        const unsigned int wb = (unsigned int)(ol * 2048 + vq * 256);
#pragma unroll
        for (int r = 0; r < 4; r++) {
#pragma unroll
            for (int q = 0; q < 4; q++) {
                unsigned int off = wb + (unsigned int)(r * 64 + q * 16);
                float4 f = *(const float4*)((const char*)Ws + swz(off));
                wp[r][q * 2 + 0] = ((u64)__float_as_uint(f.y) << 32) | __float_as_uint(f.x);
                wp[r][q * 2 + 1] = ((u64)__float_as_uint(f.w) << 32) | __float_as_uint(f.z);
            }
        }
    }

    const int o = o0 + ol;
#pragma unroll 2
    for (int b = 0; b < B; b++) {
        u64 xp[8];
#pragma unroll
        for (int q = 0; q < 4; q++) {
            float4 f = *(const float4*)(Xs + b * VI + q * 4);
            xp[q * 2 + 0] = ((u64)__float_as_uint(f.y) << 32) | __float_as_uint(f.x);
            xp[q * 2 + 1] = ((u64)__float_as_uint(f.w) << 32) | __float_as_uint(f.z);
        }
        u64 a0 = 0ull, a1 = 0ull, a2 = 0ull, a3 = 0ull;
#pragma unroll
        for (int j = 0; j < 8; j++) {
            a0 = ffma2(wp[0][j], xp[j], a0);
            a1 = ffma2(wp[1][j], xp[j], a1);
            a2 = ffma2(wp[2][j], xp[j], a2);
            a3 = ffma2(wp[3][j], xp[j], a3);
        }
        float l0, h0, l1, h1, l2, h2, l3, h3;
        upk2(a0, l0, h0); upk2(a1, l1, h1);
        upk2(a2, l2, h2); upk2(a3, l3, h3);
        __half2 p0h = __floats2half2_rn(l0 + h0, l1 + h1);
        __half2 p1h = __floats2half2_rn(l2 + h2, l3 + h3);
        float2 pk;
        pk.x = __uint_as_float(*(unsigned int*)&p0h);
        pk.y = __uint_as_float(*(unsigned int*)&p1h);
        size_t hidx = (((size_t)b * I + i) * O + o) * VO + (size_t)vq * 4;
        __stcs((float2*)(g_uhat + hidx), pk);
    }
}

// ---------------------------------------------------------------------------
// S0 pass: S0[b,o,v] = sum_i u_hat. Thread owns (b,o,q,c): q = uint2 column
// (4 v's), c one of 4 i-chunks; atomicAdd tail into zeroed S0. 65536 threads.
// ---------------------------------------------------------------------------
__global__ void __launch_bounds__(256) s0_kernel() {
    int t = blockIdx.x * 256 + threadIdx.x;   // 0 .. 65535
    int q = t & 7;
    int o = (t >> 3) & 63;
    int c = (t >> 9) & 3;
    int b = t >> 11;

    const uint2* up = (const uint2*)g_uhat;
    size_t base = (((size_t)b * I + (size_t)c * 512) * O + (size_t)o) * 8 + q;
    const size_t istride = (size_t)O * 8;

    float a0 = 0.f, a1 = 0.f, a2 = 0.f, a3 = 0.f;
#pragma unroll 8
    for (int i = 0; i < 512; i++) {
        uint2 h = __ldcs(&up[base + (size_t)i * istride]);
        float2 f0 = __half22float2(*(const __half2*)&h.x);
        float2 f1 = __half22float2(*(const __half2*)&h.y);
        a0 += f0.x; a1 += f0.y; a2 += f1.x; a3 += f1.y;
    }
    float* sp = g_S0 + (size_t)(b * O + o) * VO + q * 4;
    atomicAdd(&sp[0], a0); atomicAdd(&sp[1], a1);
    atomicAdd(&sp[2], a2); atomicAdd(&sp[3], a3);
}

// ---------------------------------------------------------------------------
// P1/P2: warp-autonomous routing pass. Warp = (b, 32 i's). Lane owns
// o0=2*lane, o1=2*lane+1 -> each lane reads its 128B CONTIGUOUS pair of rows
// (coalesced, nL=4/LDG). Softmax over 64 o's via shuffles; S in regs;
// atomicAdd tail.
// ---------------------------------------------------------------------------
__global__ void __launch_bounds__(128) p1_kernel(int pass) {
    const int gw = blockIdx.x * (blockDim.x >> 5) + (threadIdx.x >> 5);
    const int lane = threadIdx.x & 31;
    const int b = gw >> 6;
    const int i0 = (gw & 63) * 32;
    float* Sout = (pass == 1) ? g_S1 : g_S2;

    const int oA = 2 * lane, oB = 2 * lane + 1;

    float va[VO], vb[VO];
    {
        const float4* vp = (const float4*)(g_Vacc + (size_t)(b * O + oA) * VO);
#pragma unroll
        for (int j = 0; j < 8; j++) {
            float4 t4 = vp[j];
            va[4 * j + 0] = t4.x; va[4 * j + 1] = t4.y; va[4 * j + 2] = t4.z; va[4 * j + 3] = t4.w;
            float4 s4 = vp[j + 8];
            vb[4 * j + 0] = s4.x; vb[4 * j + 1] = s4.y; vb[4 * j + 2] = s4.z; vb[4 * j + 3] = s4.w;
        }
    }

    float sa[VO], sb[VO];
#pragma unroll
    for (int v = 0; v < VO; v++) { sa[v] = 0.f; sb[v] = 0.f; }

    for (int ic = 0; ic < 32; ic++) {
        const int i = i0 + ic;
        // lane's contiguous 128B: rows oA, oB
        const uint4* up = (const uint4*)(g_uhat + (((size_t)b * I + i) * O + oA) * VO);
        uint4 h0 = __ldcs(up + 0);
        uint4 h1 = __ldcs(up + 1);
        uint4 h2 = __ldcs(up + 2);
        uint4 h3 = __ldcs(up + 3);
        uint4 g0 = __ldcs(up + 4);
        uint4 g1 = __ldcs(up + 5);
        uint4 g2 = __ldcs(up + 6);
        uint4 g3 = __ldcs(up + 7);

        unsigned int r0[16] = {h0.x, h0.y, h0.z, h0.w, h1.x, h1.y, h1.z, h1.w,
                               h2.x, h2.y, h2.z, h2.w, h3.x, h3.y, h3.z, h3.w};
        unsigned int r1[16] = {g0.x, g0.y, g0.z, g0.w, g1.x, g1.y, g1.z, g1.w,
                               g2.x, g2.y, g2.z, g2.w, g3.x, g3.y, g3.z, g3.w};

        float d0 = 0.f, d1 = 0.f;
#pragma unroll
        for (int j = 0; j < 16; j++) {
            float2 f0 = __half22float2(*(const __half2*)&r0[j]);
            d0 = fmaf(f0.x, va[2 * j + 0], d0);
            d0 = fmaf(f0.y, va[2 * j + 1], d0);
            float2 f1 = __half22float2(*(const __half2*)&r1[j]);
            d1 = fmaf(f1.x, vb[2 * j + 0], d1);
            d1 = fmaf(f1.y, vb[2 * j + 1], d1);
        }

        float m = fmaxf(d0, d1);
#pragma unroll
        for (int off = 16; off; off >>= 1)
            m = fmaxf(m, __shfl_xor_sync(0xffffffffu, m, off));
        float e0 = __expf(d0 - m);
        float e1 = __expf(d1 - m);
        float es = e0 + e1;
#pragma unroll
        for (int off = 16; off; off >>= 1)
            es += __shfl_xor_sync(0xffffffffu, es, off);
        float inv = __frcp_rn(es);
        float c0 = e0 * inv;
        float c1 = e1 * inv;

#pragma unroll
        for (int j = 0; j < 16; j++) {
            float2 f0 = __half22float2(*(const __half2*)&r0[j]);
            sa[2 * j + 0] = fmaf(c0, f0.x, sa[2 * j + 0]);
            sa[2 * j + 1] = fmaf(c0, f0.y, sa[2 * j + 1]);
            float2 f1 = __half22float2(*(const __half2*)&r1[j]);
            sb[2 * j + 0] = fmaf(c1, f1.x, sb[2 * j + 0]);
            sb[2 * j + 1] = fmaf(c1, f1.y, sb[2 * j + 1]);
        }
    }

    float* sp0 = Sout + (size_t)(b * O + oA) * VO;
#pragma unroll
    for (int v = 0; v < VO; v++) {
        atomicAdd(&sp0[v], sa[v]);
        atomicAdd(&sp0[VO + v], sb[v]);
    }
}

// ---------------------------------------------------------------------------
// Squash. which==0: v0=squash(S0/64), Vacc=v0.
//         which==1: v1=squash(S1),   Vacc+=v1.
//         which==2: out=squash(S2).
// ---------------------------------------------------------------------------
__global__ void kv_kernel(int which, float* __restrict__ out) {
    int wid = threadIdx.x >> 5;
    int lane = threadIdx.x & 31;
    int pair = blockIdx.x * (blockDim.x >> 5) + wid;
    if (pair >= B * O) return;
    int idx = pair * VO + lane;

    float s;
    if (which == 0)      s = g_S0[idx] * (1.0f / (float)O);
    else if (which == 1) s = g_S1[idx];
    else                 s = g_S2[idx];

    float sq = s * s;
#pragma unroll
    for (int off = 16; off; off >>= 1)
        sq += __shfl_xor_sync(0xffffffffu, sq, off);

    float scale = (sq / (1.0f + sq)) * rsqrtf(sq + 1e-8f);
    float v = s * scale;

    if (which == 0)      g_Vacc[idx] = v;
    else if (which == 1) g_Vacc[idx] += v;
    else                 out[idx] = v;
}

// ---------------------------------------------------------------------------
extern "C" void kernel_launch(void* const* d_in, const int* in_sizes, int n_in,
                              void* d_out, int out_size) {
    const float* x;
    const float* W;
    if (in_sizes[0] == B * I * VI) {
        x = (const float*)d_in[0];
        W = (const float*)d_in[1];
    } else {
        x = (const float*)d_in[1];
        W = (const float*)d_in[0];
    }
    float* out = (float*)d_out;

    zero_kernel<<<(B * O * VO + 255) / 256, 256>>>();

    // P0: u_hat (fp16)
    p0_kernel<<<dim3(I, O / OG), 128>>>(W, x);

    // Iteration 0 (uniform coupling): S0 = sum_i u_hat
    s0_kernel<<<256, 256>>>();
    kv_kernel<<<64, 1024>>>(0, out);   // v0 = squash(S0/64); Vacc = v0

    // Iteration 1: logits = u_hat . v0
    p1_kernel<<<512, 128>>>(1);
    kv_kernel<<<64, 1024>>>(1, out);   // v1 = squash(S1); Vacc = v0 + v1

    // Iteration 2: logits = u_hat . (v0 + v1)
    p1_kernel<<<512, 128>>>(2);
    kv_kernel<<<64, 1024>>>(2, out);   // out = squash(S2)
}